// round 10
// baseline (speedup 1.0000x reference)
#include <cuda_runtime.h>
#include <cuda_fp16.h>

// Problem constants
#define N_ITEMS 20000
#define N_REC   8
#define N_USERS 2048
#define U4      (N_USERS / 4)          // 512 float4 columns
#define GRID    296                    // 148 SMs x 2 CTAs, co-resident
#define ITEMS_PER_CTA 68               // 296*68 = 20128 >= 20000 (blocked assignment)
#define S_ITEMS 27                     // items whose scores live in SMEM (108KB/CTA)
#define SMEM_BYTES (S_ITEMS * N_USERS * 2)   // 110592 B

// Scratch: fp16 intermediate for the non-SMEM items (128B-aligned for L2 line
// discard), per-user max (float bits). Device globals zero-init at load; the
// kernel epilogue restores g_max and barrier state for the next graph replay.
__device__ __align__(128) __half g_scores[(size_t)N_ITEMS * N_USERS];
__device__ float    g_max[N_USERS];
__device__ unsigned g_cnt1 = 0;
__device__ unsigned g_flag1 = 0;
__device__ unsigned g_cnt2 = 0;

__global__ void __launch_bounds__(512, 2) fused_kernel(
    const float4* __restrict__ in,   // [N_ITEMS*N_REC, U4]
    const float*  __restrict__ w,    // [8]
    float4*       __restrict__ out)  // [N_ITEMS, U4]
{
    extern __shared__ uint2 s_sc[];  // [S_ITEMS][U4] packed fp16x4 scores

    const int u4 = threadIdx.x;      // 0..511: one float4 column per thread

    float wr[N_REC];
#pragma unroll
    for (int r = 0; r < N_REC; ++r) wr[r] = __ldg(&w[r]);

    uint2* sc16 = (uint2*)g_scores;
    const int i0 = blockIdx.x * ITEMS_PER_CTA;

    // ---------------- Phase 1: scores + per-column max ----------------
    float mx = 0.f, my = 0.f, mz = 0.f, mw = 0.f;

    for (int k = 0; k < ITEMS_PER_CTA; ++k) {
        const int i = i0 + k;
        if (i >= N_ITEMS) break;
        const float4* row = in + (size_t)i * N_REC * U4 + u4;
        float sx = 0.f, sy = 0.f, sz = 0.f, sw = 0.f;
#pragma unroll
        for (int r = 0; r < N_REC; ++r) {
            float4 v = __ldcs(row + (size_t)r * U4);   // read-once streaming
            sx = fmaf(v.x, wr[r], sx);
            sy = fmaf(v.y, wr[r], sy);
            sz = fmaf(v.z, wr[r], sz);
            sw = fmaf(v.w, wr[r], sw);
        }
        __half2 h0 = __floats2half2_rn(sx, sy);
        __half2 h1 = __floats2half2_rn(sz, sw);
        uint2 packed;
        packed.x = *(unsigned int*)&h0;
        packed.y = *(unsigned int*)&h1;
        if (k < S_ITEMS)
            s_sc[k * U4 + u4] = packed;                // SMEM-resident: off LTS path
        else
            sc16[(size_t)i * U4 + u4] = packed;        // L2-resident scratch

        mx = fmaxf(mx, sx);
        my = fmaxf(my, sy);
        mz = fmaxf(mz, sz);
        mw = fmaxf(mw, sw);
    }

    // Non-negative floats: int bit ordering == float ordering.
    int* gm = (int*)g_max;
    atomicMax(&gm[u4 * 4 + 0], __float_as_int(mx));
    atomicMax(&gm[u4 * 4 + 1], __float_as_int(my));
    atomicMax(&gm[u4 * 4 + 2], __float_as_int(mz));
    atomicMax(&gm[u4 * 4 + 3], __float_as_int(mw));

    // ---------------- Grid barrier (all 296 CTAs co-resident) ----------------
    __threadfence();      // maxes visible before arrival
    __syncthreads();
    if (threadIdx.x == 0) {
        unsigned t = atomicAdd(&g_cnt1, 1u);
        if (t == GRID - 1) {
            *(volatile unsigned*)&g_flag1 = 1u;        // release
        } else {
            while (*(volatile unsigned*)&g_flag1 == 0u) __nanosleep(32);
        }
        __threadfence();  // acquire: order subsequent g_max reads after flag
    }
    __syncthreads();

    // Per-thread reciprocals of the global column maxes (read via L2).
    float4 m4 = __ldcg((const float4*)g_max + u4);
    float4 inv;
    inv.x = 1.0f / m4.x;
    inv.y = 1.0f / m4.y;
    inv.z = 1.0f / m4.z;
    inv.w = 1.0f / m4.w;

    // ---------------- Phase 2: normalize ----------------
    // Reverse order: L2-scratch items first (hottest in L2), SMEM items last.
    // Each thread reads only scores it wrote itself -> no __syncthreads needed
    // for the smem path.
    for (int k = ITEMS_PER_CTA - 1; k >= 0; --k) {
        const int i = i0 + k;
        if (i >= N_ITEMS) continue;
        const size_t idx = (size_t)i * U4 + u4;

        uint2 packed;
        if (k < S_ITEMS) {
            packed = s_sc[k * U4 + u4];
        } else {
            packed = __ldcs((const uint2*)sc16 + idx);  // dead after read
        }
        __half2 h0 = *(__half2*)&packed.x;
        __half2 h1 = *(__half2*)&packed.y;
        float2 f0 = __half22float2(h0);
        float2 f1 = __half22float2(h1);
        float4 o;
        o.x = f0.x * inv.x;
        o.y = f0.y * inv.y;
        o.z = f1.x * inv.z;
        o.w = f1.y * inv.w;
        __stcs(&out[idx], o);                            // final write, no reuse

        // Drop dead L2 scratch lines without writeback. 16 consecutive u4
        // threads share one 128B line within the same warp; values already
        // consumed above.
        if (k >= S_ITEMS && (u4 & 15) == 0) {
            const uint2* line = sc16 + idx;   // 128B-aligned (u4 mult of 16)
            asm volatile("discard.global.L2 [%0], 128;" :: "l"(line) : "memory");
        }
    }

    // ---------------- Epilogue: last CTA resets state for next replay ----------------
    __shared__ unsigned s_last;
    __syncthreads();
    if (threadIdx.x == 0) {
        __threadfence();
        unsigned t = atomicAdd(&g_cnt2, 1u);
        s_last = (t == GRID - 1) ? 1u : 0u;
    }
    __syncthreads();
    if (s_last) {
        // All CTAs have passed their g_max reads (program order before cnt2 arrive).
        for (int u = threadIdx.x; u < N_USERS; u += 512)
            *(volatile float*)&g_max[u] = 0.0f;
        __syncthreads();
        if (threadIdx.x == 0) {
            *(volatile unsigned*)&g_cnt1  = 0u;
            *(volatile unsigned*)&g_flag1 = 0u;
            *(volatile unsigned*)&g_cnt2  = 0u;
            __threadfence();
        }
    }
}

extern "C" void kernel_launch(void* const* d_in, const int* in_sizes, int n_in,
                              void* d_out, int out_size)
{
    const float4* in = (const float4*)d_in[0];   // input [160000, 2048] f32
    const float*  w  = (const float*)d_in[1];    // w [1, 8] f32
    float4* out = (float4*)d_out;                // [20000, 2048] f32

    // Opt into >48KB dynamic smem (idempotent; not a stream op, capture-safe).
    cudaFuncSetAttribute(fused_kernel,
                         cudaFuncAttributeMaxDynamicSharedMemorySize, SMEM_BYTES);

    fused_kernel<<<GRID, 512, SMEM_BYTES>>>(in, w, out);
}

// round 11
// speedup vs baseline: 1.0059x; 1.0059x over previous
#include <cuda_runtime.h>
#include <cuda_fp16.h>

// Problem constants
#define N_ITEMS 20000
#define N_REC   8
#define N_USERS 2048
#define U4      (N_USERS / 4)          // 512 float4 columns
#define GRID    296                    // 148 SMs x 2 CTAs, co-resident
#define S_ITEMS 27                     // first 27 grid-stride iterations -> SMEM (108KB/CTA)
#define SMEM_BYTES (S_ITEMS * N_USERS * 2)   // 110592 B

// Scratch: fp16 intermediate for the non-SMEM items (128B-aligned for L2 line
// discard), per-user max (float bits). Device globals zero-init at load; the
// kernel epilogue restores g_max and barrier state for the next graph replay.
__device__ __align__(128) __half g_scores[(size_t)N_ITEMS * N_USERS];
__device__ float    g_max[N_USERS];
__device__ unsigned g_cnt1 = 0;
__device__ unsigned g_flag1 = 0;
__device__ unsigned g_cnt2 = 0;

__global__ void __launch_bounds__(512, 2) fused_kernel(
    const float4* __restrict__ in,   // [N_ITEMS*N_REC, U4]
    const float*  __restrict__ w,    // [8]
    float4*       __restrict__ out)  // [N_ITEMS, U4]
{
    extern __shared__ uint2 s_sc[];  // [S_ITEMS][U4] packed fp16x4 scores

    const int u4 = threadIdx.x;      // 0..511: one float4 column per thread

    float wr[N_REC];
#pragma unroll
    for (int r = 0; r < N_REC; ++r) wr[r] = __ldg(&w[r]);

    uint2* sc16 = (uint2*)g_scores;

    // ---------------- Phase 1: scores + per-column max ----------------
    // Interleaved grid-stride (i = bid + k*GRID): all CTAs sweep one dense
    // window together -> DRAM row-buffer friendly (R7-proven pattern).
    float mx = 0.f, my = 0.f, mz = 0.f, mw = 0.f;

    int k = 0;
    for (int i = blockIdx.x; i < N_ITEMS; i += GRID, ++k) {
        const float4* row = in + (size_t)i * N_REC * U4 + u4;
        float sx = 0.f, sy = 0.f, sz = 0.f, sw = 0.f;
#pragma unroll
        for (int r = 0; r < N_REC; ++r) {
            float4 v = __ldcs(row + (size_t)r * U4);   // read-once streaming
            sx = fmaf(v.x, wr[r], sx);
            sy = fmaf(v.y, wr[r], sy);
            sz = fmaf(v.z, wr[r], sz);
            sw = fmaf(v.w, wr[r], sw);
        }
        __half2 h0 = __floats2half2_rn(sx, sy);
        __half2 h1 = __floats2half2_rn(sz, sw);
        uint2 packed;
        packed.x = *(unsigned int*)&h0;
        packed.y = *(unsigned int*)&h1;
        if (k < S_ITEMS)
            s_sc[k * U4 + u4] = packed;                // SMEM: off the LTS path
        else
            sc16[(size_t)i * U4 + u4] = packed;        // L2-resident scratch

        mx = fmaxf(mx, sx);
        my = fmaxf(my, sy);
        mz = fmaxf(mz, sz);
        mw = fmaxf(mw, sw);
    }

    // Non-negative floats: int bit ordering == float ordering.
    int* gm = (int*)g_max;
    atomicMax(&gm[u4 * 4 + 0], __float_as_int(mx));
    atomicMax(&gm[u4 * 4 + 1], __float_as_int(my));
    atomicMax(&gm[u4 * 4 + 2], __float_as_int(mz));
    atomicMax(&gm[u4 * 4 + 3], __float_as_int(mw));

    // ---------------- Grid barrier (all 296 CTAs co-resident) ----------------
    __threadfence();      // maxes visible before arrival
    __syncthreads();
    if (threadIdx.x == 0) {
        unsigned t = atomicAdd(&g_cnt1, 1u);
        if (t == GRID - 1) {
            *(volatile unsigned*)&g_flag1 = 1u;        // release
        } else {
            while (*(volatile unsigned*)&g_flag1 == 0u) __nanosleep(32);
        }
        __threadfence();  // acquire: order subsequent g_max reads after flag
    }
    __syncthreads();

    // Per-thread reciprocals of the global column maxes (read via L2).
    float4 m4 = __ldcg((const float4*)g_max + u4);
    float4 inv;
    inv.x = 1.0f / m4.x;
    inv.y = 1.0f / m4.y;
    inv.z = 1.0f / m4.z;
    inv.w = 1.0f / m4.w;

    // ---------------- Phase 2: normalize (reverse: hottest L2 lines first) --
    // Each thread reads only scores it wrote itself -> no sync for smem path.
    const int kmax = (N_ITEMS - 1 - blockIdx.x) / GRID;
    for (int kk = kmax; kk >= 0; --kk) {
        const int i = blockIdx.x + kk * GRID;
        const size_t idx = (size_t)i * U4 + u4;

        uint2 packed;
        if (kk < S_ITEMS) {
            packed = s_sc[kk * U4 + u4];
        } else {
            packed = __ldcs((const uint2*)sc16 + idx);  // dead after read
        }
        __half2 h0 = *(__half2*)&packed.x;
        __half2 h1 = *(__half2*)&packed.y;
        float2 f0 = __half22float2(h0);
        float2 f1 = __half22float2(h1);
        float4 o;
        o.x = f0.x * inv.x;
        o.y = f0.y * inv.y;
        o.z = f1.x * inv.z;
        o.w = f1.y * inv.w;
        __stcs(&out[idx], o);                            // final write, no reuse

        // Drop dead L2 scratch lines without writeback. 16 consecutive u4
        // threads share one 128B line within the same warp; values already
        // consumed above.
        if (kk >= S_ITEMS && (u4 & 15) == 0) {
            const uint2* line = sc16 + idx;   // 128B-aligned (u4 mult of 16)
            asm volatile("discard.global.L2 [%0], 128;" :: "l"(line) : "memory");
        }
    }

    // ---------------- Epilogue: last CTA resets state for next replay -------
    __shared__ unsigned s_last;
    __syncthreads();
    if (threadIdx.x == 0) {
        __threadfence();
        unsigned t = atomicAdd(&g_cnt2, 1u);
        s_last = (t == GRID - 1) ? 1u : 0u;
    }
    __syncthreads();
    if (s_last) {
        // All CTAs have passed their g_max reads (program order before cnt2).
        for (int u = threadIdx.x; u < N_USERS; u += 512)
            *(volatile float*)&g_max[u] = 0.0f;
        __syncthreads();
        if (threadIdx.x == 0) {
            *(volatile unsigned*)&g_cnt1  = 0u;
            *(volatile unsigned*)&g_flag1 = 0u;
            *(volatile unsigned*)&g_cnt2  = 0u;
            __threadfence();
        }
    }
}

extern "C" void kernel_launch(void* const* d_in, const int* in_sizes, int n_in,
                              void* d_out, int out_size)
{
    const float4* in = (const float4*)d_in[0];   // input [160000, 2048] f32
    const float*  w  = (const float*)d_in[1];    // w [1, 8] f32
    float4* out = (float4*)d_out;                // [20000, 2048] f32

    // Opt into >48KB dynamic smem (idempotent; not a stream op, capture-safe).
    cudaFuncSetAttribute(fused_kernel,
                         cudaFuncAttributeMaxDynamicSharedMemorySize, SMEM_BYTES);

    fused_kernel<<<GRID, 512, SMEM_BYTES>>>(in, w, out);
}

// round 12
// speedup vs baseline: 1.0156x; 1.0097x over previous
#include <cuda_runtime.h>
#include <cuda_fp16.h>

// Problem constants
#define N_ITEMS 20000
#define N_REC   8
#define N_USERS 2048
#define U4      (N_USERS / 4)          // 512 float4 columns
#define GRID    296                    // 148 SMs x 2 CTAs, co-resident
#define S_ITEMS 27                     // first 27 grid-stride iters -> SMEM (108KB/CTA)
#define SMEM_BYTES (S_ITEMS * N_USERS * 2)   // 110592 B

// Scratch: fp16 intermediate for non-SMEM items (128B-aligned for L2 line
// discard), per-user max (float bits). Device globals zero-init at load; the
// kernel epilogue restores g_max and barrier state for the next graph replay.
__device__ __align__(128) __half g_scores[(size_t)N_ITEMS * N_USERS];
__device__ float    g_max[N_USERS];
__device__ unsigned g_cnt1 = 0;
__device__ unsigned g_flag1 = 0;
__device__ unsigned g_cnt2 = 0;

__global__ void __launch_bounds__(512, 2) fused_kernel(
    const float4* __restrict__ in,   // [N_ITEMS*N_REC, U4]
    const float*  __restrict__ w,    // [8]
    float4*       __restrict__ out)  // [N_ITEMS, U4]
{
    extern __shared__ uint2 s_sc[];  // [S_ITEMS][U4] packed fp16x4 scores

    const int u4 = threadIdx.x;      // 0..511: one float4 column per thread

    float wr[N_REC];
#pragma unroll
    for (int r = 0; r < N_REC; ++r) wr[r] = __ldg(&w[r]);

    uint2* sc16 = (uint2*)g_scores;

    // ---------------- Phase 1: scores + per-column max ----------------
    // Interleaved grid-stride (i = bid + k*GRID), R7-proven DRAM pattern.
    // Split into two BRANCHLESS loops so ptxas can front-batch the 8 LDGs.
    float mx = 0.f, my = 0.f, mz = 0.f, mw = 0.f;

    // Loop A: first S_ITEMS iterations -> SMEM.
    // Bound check unnecessary: bid + (S_ITEMS-1)*GRID <= 295 + 26*296 < 20000.
    {
        int i = blockIdx.x;
        for (int k = 0; k < S_ITEMS; ++k, i += GRID) {
            const float4* row = in + (size_t)i * N_REC * U4 + u4;
            float sx = 0.f, sy = 0.f, sz = 0.f, sw = 0.f;
#pragma unroll
            for (int r = 0; r < N_REC; ++r) {
                float4 v = __ldcs(row + (size_t)r * U4);   // read-once streaming
                sx = fmaf(v.x, wr[r], sx);
                sy = fmaf(v.y, wr[r], sy);
                sz = fmaf(v.z, wr[r], sz);
                sw = fmaf(v.w, wr[r], sw);
            }
            __half2 h0 = __floats2half2_rn(sx, sy);
            __half2 h1 = __floats2half2_rn(sz, sw);
            uint2 packed;
            packed.x = *(unsigned int*)&h0;
            packed.y = *(unsigned int*)&h1;
            s_sc[k * U4 + u4] = packed;                    // SMEM: off the LTS path

            mx = fmaxf(mx, sx);
            my = fmaxf(my, sy);
            mz = fmaxf(mz, sz);
            mw = fmaxf(mw, sw);
        }
    }

    // Loop B: remaining iterations -> L2-resident global scratch.
    for (int i = blockIdx.x + S_ITEMS * GRID; i < N_ITEMS; i += GRID) {
        const float4* row = in + (size_t)i * N_REC * U4 + u4;
        float sx = 0.f, sy = 0.f, sz = 0.f, sw = 0.f;
#pragma unroll
        for (int r = 0; r < N_REC; ++r) {
            float4 v = __ldcs(row + (size_t)r * U4);
            sx = fmaf(v.x, wr[r], sx);
            sy = fmaf(v.y, wr[r], sy);
            sz = fmaf(v.z, wr[r], sz);
            sw = fmaf(v.w, wr[r], sw);
        }
        __half2 h0 = __floats2half2_rn(sx, sy);
        __half2 h1 = __floats2half2_rn(sz, sw);
        uint2 packed;
        packed.x = *(unsigned int*)&h0;
        packed.y = *(unsigned int*)&h1;
        sc16[(size_t)i * U4 + u4] = packed;                // default .wb: L2-resident

        mx = fmaxf(mx, sx);
        my = fmaxf(my, sy);
        mz = fmaxf(mz, sz);
        mw = fmaxf(mw, sw);
    }

    // Non-negative floats: int bit ordering == float ordering.
    int* gm = (int*)g_max;
    atomicMax(&gm[u4 * 4 + 0], __float_as_int(mx));
    atomicMax(&gm[u4 * 4 + 1], __float_as_int(my));
    atomicMax(&gm[u4 * 4 + 2], __float_as_int(mz));
    atomicMax(&gm[u4 * 4 + 3], __float_as_int(mw));

    // ---------------- Grid barrier (all 296 CTAs co-resident) ----------------
    __threadfence();      // maxes visible before arrival
    __syncthreads();
    if (threadIdx.x == 0) {
        unsigned t = atomicAdd(&g_cnt1, 1u);
        if (t == GRID - 1) {
            *(volatile unsigned*)&g_flag1 = 1u;            // release
        } else {
            while (*(volatile unsigned*)&g_flag1 == 0u) __nanosleep(32);
        }
        __threadfence();  // acquire: order subsequent g_max reads after flag
    }
    __syncthreads();

    // Per-thread reciprocals of the global column maxes (read via L2).
    float4 m4 = __ldcg((const float4*)g_max + u4);
    float4 inv;
    inv.x = 1.0f / m4.x;
    inv.y = 1.0f / m4.y;
    inv.z = 1.0f / m4.z;
    inv.w = 1.0f / m4.w;

    // ---------------- Phase 2: normalize ----------------
    // Loop B' first (reverse: hottest L2 lines first), then SMEM loop A'.
    const int kmax = (N_ITEMS - 1 - blockIdx.x) / GRID;
    for (int kk = kmax; kk >= S_ITEMS; --kk) {
        const int i = blockIdx.x + kk * GRID;
        const size_t idx = (size_t)i * U4 + u4;
        uint2 packed = __ldcs((const uint2*)sc16 + idx);   // dead after read
        __half2 h0 = *(__half2*)&packed.x;
        __half2 h1 = *(__half2*)&packed.y;
        float2 f0 = __half22float2(h0);
        float2 f1 = __half22float2(h1);
        float4 o;
        o.x = f0.x * inv.x;
        o.y = f0.y * inv.y;
        o.z = f1.x * inv.z;
        o.w = f1.y * inv.w;
        __stcs(&out[idx], o);                              // final write, no reuse

        // Drop dead L2 scratch line without writeback. 16 consecutive u4
        // threads share one 128B line within the same warp; values already
        // consumed above.
        if ((u4 & 15) == 0) {
            const uint2* line = sc16 + idx;   // 128B-aligned (u4 mult of 16)
            asm volatile("discard.global.L2 [%0], 128;" :: "l"(line) : "memory");
        }
    }

    // SMEM items (each thread reads only what it wrote -> no sync needed).
    {
        int i = blockIdx.x + (S_ITEMS - 1) * GRID;
        for (int k = S_ITEMS - 1; k >= 0; --k, i -= GRID) {
            const size_t idx = (size_t)i * U4 + u4;
            uint2 packed = s_sc[k * U4 + u4];
            __half2 h0 = *(__half2*)&packed.x;
            __half2 h1 = *(__half2*)&packed.y;
            float2 f0 = __half22float2(h0);
            float2 f1 = __half22float2(h1);
            float4 o;
            o.x = f0.x * inv.x;
            o.y = f0.y * inv.y;
            o.z = f1.x * inv.z;
            o.w = f1.y * inv.w;
            __stcs(&out[idx], o);
        }
    }

    // ---------------- Epilogue: last CTA resets state for next replay -------
    __shared__ unsigned s_last;
    __syncthreads();
    if (threadIdx.x == 0) {
        __threadfence();
        unsigned t = atomicAdd(&g_cnt2, 1u);
        s_last = (t == GRID - 1) ? 1u : 0u;
    }
    __syncthreads();
    if (s_last) {
        // All CTAs have passed their g_max reads (program order before cnt2).
        for (int u = threadIdx.x; u < N_USERS; u += 512)
            *(volatile float*)&g_max[u] = 0.0f;
        __syncthreads();
        if (threadIdx.x == 0) {
            *(volatile unsigned*)&g_cnt1  = 0u;
            *(volatile unsigned*)&g_flag1 = 0u;
            *(volatile unsigned*)&g_cnt2  = 0u;
            __threadfence();
        }
    }
}

extern "C" void kernel_launch(void* const* d_in, const int* in_sizes, int n_in,
                              void* d_out, int out_size)
{
    const float4* in = (const float4*)d_in[0];   // input [160000, 2048] f32
    const float*  w  = (const float*)d_in[1];    // w [1, 8] f32
    float4* out = (float4*)d_out;                // [20000, 2048] f32

    // Opt into >48KB dynamic smem (idempotent; not a stream op, capture-safe).
    cudaFuncSetAttribute(fused_kernel,
                         cudaFuncAttributeMaxDynamicSharedMemorySize, SMEM_BYTES);

    fused_kernel<<<GRID, 512, SMEM_BYTES>>>(in, w, out);
}

// round 13
// speedup vs baseline: 1.1004x; 1.0835x over previous
#include <cuda_runtime.h>
#include <cuda_fp16.h>

// Problem constants
#define N_ITEMS 20000
#define N_REC   8
#define N_USERS 2048
#define U4      (N_USERS / 4)          // 512 float4 columns
#define GRID    296                    // 148 SMs x 2 CTAs, co-resident
#define CHUNK   4                      // items per work-steal grab (20000 % 4 == 0)

// Scratch: fp16 intermediate scores (82 MB, 128B-aligned for L2 line discard),
// per-user max (float bits). Device globals are zero-initialized at load; the
// kernel epilogue restores all mutable state for the next graph replay.
__device__ __align__(128) __half g_scores[(size_t)N_ITEMS * N_USERS];
__device__ float    g_max[N_USERS];
__device__ unsigned g_ctr  = 0;        // phase-1 work-stealing counter
__device__ unsigned g_cnt1 = 0;
__device__ unsigned g_flag1 = 0;
__device__ unsigned g_cnt2 = 0;

__global__ void __launch_bounds__(512, 2) fused_kernel(
    const float4* __restrict__ in,   // [N_ITEMS*N_REC, U4]
    const float*  __restrict__ w,    // [8]
    float4*       __restrict__ out)  // [N_ITEMS, U4]
{
    const int u4 = threadIdx.x;      // 0..511: one float4 column per thread

    float wr[N_REC];
#pragma unroll
    for (int r = 0; r < N_REC; ++r) wr[r] = __ldg(&w[r]);

    uint2* sc16 = (uint2*)g_scores;

    // ---------------- Phase 1: scores + per-column max (work stealing) ------
    // Chunk-ordered grabs keep the chip-wide sweep dense and forward-moving
    // (R7's DRAM-friendly pattern) while equalizing CTA finish times so the
    // grid barrier below wastes minimal time on cross-CTA spread.
    float mx = 0.f, my = 0.f, mz = 0.f, mw = 0.f;

    __shared__ unsigned s_base;
    for (;;) {
        __syncthreads();
        if (threadIdx.x == 0) s_base = atomicAdd(&g_ctr, CHUNK);
        __syncthreads();
        const unsigned base = s_base;
        if (base >= N_ITEMS) break;

#pragma unroll
        for (int j = 0; j < CHUNK; ++j) {
            const int i = base + j;                       // 20000 % 4 == 0: no tail
            const float4* row = in + (size_t)i * N_REC * U4 + u4;
            float sx = 0.f, sy = 0.f, sz = 0.f, sw = 0.f;
#pragma unroll
            for (int r = 0; r < N_REC; ++r) {
                float4 v = __ldcs(row + (size_t)r * U4);  // read-once streaming
                sx = fmaf(v.x, wr[r], sx);
                sy = fmaf(v.y, wr[r], sy);
                sz = fmaf(v.z, wr[r], sz);
                sw = fmaf(v.w, wr[r], sw);
            }
            __half2 h0 = __floats2half2_rn(sx, sy);
            __half2 h1 = __floats2half2_rn(sz, sw);
            uint2 packed;
            packed.x = *(unsigned int*)&h0;
            packed.y = *(unsigned int*)&h1;
            sc16[(size_t)i * U4 + u4] = packed;           // default .wb: L2-resident

            mx = fmaxf(mx, sx);
            my = fmaxf(my, sy);
            mz = fmaxf(mz, sz);
            mw = fmaxf(mw, sw);
        }
    }

    // Non-negative floats: int bit ordering == float ordering.
    int* gm = (int*)g_max;
    atomicMax(&gm[u4 * 4 + 0], __float_as_int(mx));
    atomicMax(&gm[u4 * 4 + 1], __float_as_int(my));
    atomicMax(&gm[u4 * 4 + 2], __float_as_int(mz));
    atomicMax(&gm[u4 * 4 + 3], __float_as_int(mw));

    // ---------------- Grid barrier (all 296 CTAs co-resident) ----------------
    __threadfence();      // maxes visible before arrival
    __syncthreads();
    if (threadIdx.x == 0) {
        unsigned t = atomicAdd(&g_cnt1, 1u);
        if (t == GRID - 1) {
            *(volatile unsigned*)&g_flag1 = 1u;           // release
        } else {
            while (*(volatile unsigned*)&g_flag1 == 0u) __nanosleep(32);
        }
        __threadfence();  // acquire: order subsequent g_max reads after flag
    }
    __syncthreads();

    // Per-thread reciprocals of the global column maxes (read via L2).
    float4 m4 = __ldcg((const float4*)g_max + u4);
    float4 inv;
    inv.x = 1.0f / m4.x;
    inv.y = 1.0f / m4.y;
    inv.z = 1.0f / m4.z;
    inv.w = 1.0f / m4.w;

    // ---------------- Phase 2: normalize (static reverse interleave) --------
    // Reverse order: most-recently-written scratch lines (hottest in L2) first.
    const int kmax = (N_ITEMS - 1 - blockIdx.x) / GRID;
    for (int k = kmax; k >= 0; --k) {
        const int i = blockIdx.x + k * GRID;
        const size_t idx = (size_t)i * U4 + u4;
        uint2 packed = __ldcs((const uint2*)sc16 + idx);  // dead after read
        __half2 h0 = *(__half2*)&packed.x;
        __half2 h1 = *(__half2*)&packed.y;
        float2 f0 = __half22float2(h0);
        float2 f1 = __half22float2(h1);
        float4 o;
        o.x = f0.x * inv.x;
        o.y = f0.y * inv.y;
        o.z = f1.x * inv.z;
        o.w = f1.y * inv.w;
        __stcs(&out[idx], o);                             // final write, no reuse

        // Scratch line is dead: drop it from L2 without writeback. 16
        // consecutive u4 threads share one 128B line within the same warp;
        // values already consumed above.
        if ((u4 & 15) == 0) {
            const uint2* line = sc16 + idx;   // 128B-aligned (u4 mult of 16)
            asm volatile("discard.global.L2 [%0], 128;" :: "l"(line) : "memory");
        }
    }

    // ---------------- Epilogue: last CTA resets state for next replay -------
    __shared__ unsigned s_last;
    __syncthreads();
    if (threadIdx.x == 0) {
        __threadfence();
        unsigned t = atomicAdd(&g_cnt2, 1u);
        s_last = (t == GRID - 1) ? 1u : 0u;
    }
    __syncthreads();
    if (s_last) {
        // All CTAs have passed their g_max reads (program order before cnt2).
        for (int u = threadIdx.x; u < N_USERS; u += 512)
            *(volatile float*)&g_max[u] = 0.0f;
        __syncthreads();
        if (threadIdx.x == 0) {
            *(volatile unsigned*)&g_ctr   = 0u;
            *(volatile unsigned*)&g_cnt1  = 0u;
            *(volatile unsigned*)&g_flag1 = 0u;
            *(volatile unsigned*)&g_cnt2  = 0u;
            __threadfence();
        }
    }
}

extern "C" void kernel_launch(void* const* d_in, const int* in_sizes, int n_in,
                              void* d_out, int out_size)
{
    const float4* in = (const float4*)d_in[0];   // input [160000, 2048] f32
    const float*  w  = (const float*)d_in[1];    // w [1, 8] f32
    float4* out = (float4*)d_out;                // [20000, 2048] f32

    fused_kernel<<<GRID, 512>>>(in, w, out);
}

// round 14
// speedup vs baseline: 1.1423x; 1.0381x over previous
#include <cuda_runtime.h>
#include <cuda_fp16.h>

// Problem constants
#define N_ITEMS 20000
#define N_REC   8
#define N_USERS 2048
#define U4      (N_USERS / 4)          // 512 float4 columns
#define GRID    296                    // 148 SMs x 2 CTAs, co-resident
#define CHUNK   4                      // items per work-steal grab (20000 % 4 == 0)
#define S_CHUNKS 4                     // first 4 grabbed chunks (16 items) -> SMEM
#define S_ITEMS  (S_CHUNKS * CHUNK)    // 16
#define CAP      256                   // max grabs recorded per CTA (>=15x headroom)

// Dynamic smem: [S_ITEMS*U4] uint2 score tile (64KB) + [CAP] chunk-base list.
#define SMEM_BYTES (S_ITEMS * N_USERS * 2 + CAP * 4)

// Scratch: fp16 intermediate for non-SMEM items (128B-aligned for L2 line
// discard), per-user max (float bits). Device globals zero-init at load; the
// kernel epilogue restores all mutable state for the next graph replay.
__device__ __align__(128) __half g_scores[(size_t)N_ITEMS * N_USERS];
__device__ float    g_max[N_USERS];
__device__ unsigned g_ctr  = 0;        // phase-1 work-stealing counter
__device__ unsigned g_cnt1 = 0;
__device__ unsigned g_flag1 = 0;
__device__ unsigned g_cnt2 = 0;

__global__ void __launch_bounds__(512, 2) fused_kernel(
    const float4* __restrict__ in,   // [N_ITEMS*N_REC, U4]
    const float*  __restrict__ w,    // [8]
    float4*       __restrict__ out)  // [N_ITEMS, U4]
{
    extern __shared__ uint2 s_sc[];                  // [S_ITEMS][U4]
    unsigned* s_chunks = (unsigned*)(s_sc + S_ITEMS * U4);  // [CAP]
    __shared__ unsigned s_base;

    const int u4 = threadIdx.x;      // 0..511: one float4 column per thread

    float wr[N_REC];
#pragma unroll
    for (int r = 0; r < N_REC; ++r) wr[r] = __ldg(&w[r]);

    uint2* sc16 = (uint2*)g_scores;

    // ---------------- Phase 1: scores + per-column max (work stealing) ------
    // Chunk-ordered grabs keep the chip-wide sweep dense and forward-moving
    // (DRAM row-buffer friendly) while equalizing CTA finish times. Each CTA
    // records its grabbed chunks; its first S_CHUNKS chunks' scores go to
    // SMEM (off the LTS path), the rest to L2-resident global scratch.
    float mx = 0.f, my = 0.f, mz = 0.f, mw = 0.f;
    int cnt = 0;                       // uniform across the CTA

    while (cnt < CAP) {
        __syncthreads();
        if (threadIdx.x == 0) {
            unsigned b = atomicAdd(&g_ctr, CHUNK);
            s_base = b;
            if (b < N_ITEMS) s_chunks[cnt] = b;
        }
        __syncthreads();
        const unsigned base = s_base;
        if (base >= N_ITEMS) break;

        if (cnt < S_CHUNKS) {
            // SMEM-path chunk (branchless inner body)
#pragma unroll
            for (int j = 0; j < CHUNK; ++j) {
                const int i = base + j;
                const float4* row = in + (size_t)i * N_REC * U4 + u4;
                float sx = 0.f, sy = 0.f, sz = 0.f, sw = 0.f;
#pragma unroll
                for (int r = 0; r < N_REC; ++r) {
                    float4 v = __ldcs(row + (size_t)r * U4);
                    sx = fmaf(v.x, wr[r], sx);
                    sy = fmaf(v.y, wr[r], sy);
                    sz = fmaf(v.z, wr[r], sz);
                    sw = fmaf(v.w, wr[r], sw);
                }
                __half2 h0 = __floats2half2_rn(sx, sy);
                __half2 h1 = __floats2half2_rn(sz, sw);
                uint2 packed;
                packed.x = *(unsigned int*)&h0;
                packed.y = *(unsigned int*)&h1;
                s_sc[(cnt * CHUNK + j) * U4 + u4] = packed;

                mx = fmaxf(mx, sx);
                my = fmaxf(my, sy);
                mz = fmaxf(mz, sz);
                mw = fmaxf(mw, sw);
            }
        } else {
            // Global-scratch chunk (branchless inner body)
#pragma unroll
            for (int j = 0; j < CHUNK; ++j) {
                const int i = base + j;
                const float4* row = in + (size_t)i * N_REC * U4 + u4;
                float sx = 0.f, sy = 0.f, sz = 0.f, sw = 0.f;
#pragma unroll
                for (int r = 0; r < N_REC; ++r) {
                    float4 v = __ldcs(row + (size_t)r * U4);
                    sx = fmaf(v.x, wr[r], sx);
                    sy = fmaf(v.y, wr[r], sy);
                    sz = fmaf(v.z, wr[r], sz);
                    sw = fmaf(v.w, wr[r], sw);
                }
                __half2 h0 = __floats2half2_rn(sx, sy);
                __half2 h1 = __floats2half2_rn(sz, sw);
                uint2 packed;
                packed.x = *(unsigned int*)&h0;
                packed.y = *(unsigned int*)&h1;
                sc16[(size_t)i * U4 + u4] = packed;      // default .wb: L2-resident

                mx = fmaxf(mx, sx);
                my = fmaxf(my, sy);
                mz = fmaxf(mz, sz);
                mw = fmaxf(mw, sw);
            }
        }
        ++cnt;
    }

    // Non-negative floats: int bit ordering == float ordering.
    int* gm = (int*)g_max;
    atomicMax(&gm[u4 * 4 + 0], __float_as_int(mx));
    atomicMax(&gm[u4 * 4 + 1], __float_as_int(my));
    atomicMax(&gm[u4 * 4 + 2], __float_as_int(mz));
    atomicMax(&gm[u4 * 4 + 3], __float_as_int(mw));

    // ---------------- Grid barrier (all 296 CTAs co-resident) ----------------
    __threadfence();      // maxes (and s_chunks) visible before arrival
    __syncthreads();
    if (threadIdx.x == 0) {
        unsigned t = atomicAdd(&g_cnt1, 1u);
        if (t == GRID - 1) {
            *(volatile unsigned*)&g_flag1 = 1u;           // release
        } else {
            while (*(volatile unsigned*)&g_flag1 == 0u) __nanosleep(32);
        }
        __threadfence();  // acquire: order subsequent g_max reads after flag
    }
    __syncthreads();

    // Per-thread reciprocals of the global column maxes (read via L2).
    float4 m4 = __ldcg((const float4*)g_max + u4);
    float4 inv;
    inv.x = 1.0f / m4.x;
    inv.y = 1.0f / m4.y;
    inv.z = 1.0f / m4.z;
    inv.w = 1.0f / m4.w;

    // ---------------- Phase 2: normalize own grabbed chunks ----------------
    // Global-scratch chunks first in reverse grab order (hottest L2 lines
    // first), then SMEM chunks (each thread reads only what it wrote).
    for (int c = cnt - 1; c >= S_CHUNKS; --c) {
        const unsigned base = s_chunks[c];
#pragma unroll
        for (int j = 0; j < CHUNK; ++j) {
            const int i = base + j;
            const size_t idx = (size_t)i * U4 + u4;
            uint2 packed = __ldcs((const uint2*)sc16 + idx);  // dead after read
            __half2 h0 = *(__half2*)&packed.x;
            __half2 h1 = *(__half2*)&packed.y;
            float2 f0 = __half22float2(h0);
            float2 f1 = __half22float2(h1);
            float4 o;
            o.x = f0.x * inv.x;
            o.y = f0.y * inv.y;
            o.z = f1.x * inv.z;
            o.w = f1.y * inv.w;
            __stcs(&out[idx], o);                             // final write

            // Drop dead L2 scratch line without writeback. 16 consecutive u4
            // threads share one 128B line within the same warp; values already
            // consumed above.
            if ((u4 & 15) == 0) {
                const uint2* line = sc16 + idx;   // 128B-aligned
                asm volatile("discard.global.L2 [%0], 128;" :: "l"(line) : "memory");
            }
        }
    }

    {
        const int smax = (cnt < S_CHUNKS) ? cnt : S_CHUNKS;
        for (int c = smax - 1; c >= 0; --c) {
            const unsigned base = s_chunks[c];
#pragma unroll
            for (int j = 0; j < CHUNK; ++j) {
                const int i = base + j;
                const size_t idx = (size_t)i * U4 + u4;
                uint2 packed = s_sc[(c * CHUNK + j) * U4 + u4];
                __half2 h0 = *(__half2*)&packed.x;
                __half2 h1 = *(__half2*)&packed.y;
                float2 f0 = __half22float2(h0);
                float2 f1 = __half22float2(h1);
                float4 o;
                o.x = f0.x * inv.x;
                o.y = f0.y * inv.y;
                o.z = f1.x * inv.z;
                o.w = f1.y * inv.w;
                __stcs(&out[idx], o);
            }
        }
    }

    // ---------------- Epilogue: last CTA resets state for next replay -------
    __shared__ unsigned s_last;
    __syncthreads();
    if (threadIdx.x == 0) {
        __threadfence();
        unsigned t = atomicAdd(&g_cnt2, 1u);
        s_last = (t == GRID - 1) ? 1u : 0u;
    }
    __syncthreads();
    if (s_last) {
        // All CTAs have passed their g_max reads (program order before cnt2).
        for (int u = threadIdx.x; u < N_USERS; u += 512)
            *(volatile float*)&g_max[u] = 0.0f;
        __syncthreads();
        if (threadIdx.x == 0) {
            *(volatile unsigned*)&g_ctr   = 0u;
            *(volatile unsigned*)&g_cnt1  = 0u;
            *(volatile unsigned*)&g_flag1 = 0u;
            *(volatile unsigned*)&g_cnt2  = 0u;
            __threadfence();
        }
    }
}

extern "C" void kernel_launch(void* const* d_in, const int* in_sizes, int n_in,
                              void* d_out, int out_size)
{
    const float4* in = (const float4*)d_in[0];   // input [160000, 2048] f32
    const float*  w  = (const float*)d_in[1];    // w [1, 8] f32
    float4* out = (float4*)d_out;                // [20000, 2048] f32

    // Opt into >48KB dynamic smem (idempotent; not a stream op, capture-safe).
    cudaFuncSetAttribute(fused_kernel,
                         cudaFuncAttributeMaxDynamicSharedMemorySize, SMEM_BYTES);

    fused_kernel<<<GRID, 512, SMEM_BYTES>>>(in, w, out);
}